// round 1
// baseline (speedup 1.0000x reference)
#include <cuda_runtime.h>

// ---------------- problem constants ----------------
#define NB     128
#define LFULL  1024
#define CDIM   512
#define L1     1023          // L - 1
#define L2     1022          // L - 2
#define LCAT   2045          // L1 + L2
#define LOGITS_SIZE  (128l*128*2045)      // 33,505,280
#define YTRUE_OFF    (33505280l)
#define YTRUE_SIZE   (128l*2045)          // 261,760
#define ACC_OFF      (33767040l)

// scratch: pred for one step at a time, [r][c] with r = m*L_s + l
static __device__ float g_pred[128ll * 1023 * 512];
static __device__ unsigned int g_cnt[2];

// ---------------- tiny helper kernels ----------------
__global__ void k_zero() {
    if (threadIdx.x < 2) g_cnt[threadIdx.x] = 0u;
}

__global__ void k_ytrues(float* __restrict__ out) {
    long idx = (long)blockIdx.x * blockDim.x + threadIdx.x;
    if (idx < YTRUE_SIZE) out[YTRUE_OFF + idx] = (float)(idx / 2045);
}

__global__ void k_accs(float* __restrict__ out) {
    if (threadIdx.x == 0) out[ACC_OFF + 0] = (float)g_cnt[0] * (1.0f / (128.0f * 1023.0f));
    if (threadIdx.x == 1) out[ACC_OFF + 1] = (float)g_cnt[1] * (1.0f / (128.0f * 1022.0f));
}

// ---------------- kernel A: pred = P @ W^T + b ----------------
// C[r, c] for r in [by*128, by*128+128), c in [bx*128, bx*128+128)
// r = m*LS + l ; A row base = (m*1024 + l)*512 ; B row base = c*512 (W is [c][p])
template<int LS>
__global__ __launch_bounds__(256) void k_pred(const float* __restrict__ patient,
                                              const float* __restrict__ W,
                                              const float* __restrict__ bias) {
    __shared__ float As[16][128];
    __shared__ float Bs[16][128];
    __shared__ unsigned int rowA[128];

    const int tid = threadIdx.x;
    const int tx = tid & 15, ty = tid >> 4;
    const int row0 = blockIdx.y * 128;
    const int col0 = blockIdx.x * 128;

    if (tid < 128) {
        int r = row0 + tid;
        int mm = r / LS;
        int ll = r - mm * LS;
        rowA[tid] = (unsigned)(mm * 1024 + ll) * 512u;
    }
    __syncthreads();

    float acc[8][8];
#pragma unroll
    for (int i = 0; i < 8; i++)
#pragma unroll
        for (int j = 0; j < 8; j++) acc[i][j] = 0.0f;

    for (int k0 = 0; k0 < 512; k0 += 16) {
#pragma unroll
        for (int i = 0; i < 2; i++) {
            int f4 = tid + i * 256;              // 0..511
            int m  = f4 >> 2;
            int k4 = (f4 & 3) * 4;
            float4 va = *(const float4*)(patient + (long)rowA[m] + k0 + k4);
            As[k4 + 0][m] = va.x; As[k4 + 1][m] = va.y;
            As[k4 + 2][m] = va.z; As[k4 + 3][m] = va.w;
            float4 vb = *(const float4*)(W + (long)(col0 + m) * 512 + k0 + k4);
            Bs[k4 + 0][m] = vb.x; Bs[k4 + 1][m] = vb.y;
            Bs[k4 + 2][m] = vb.z; Bs[k4 + 3][m] = vb.w;
        }
        __syncthreads();
#pragma unroll
        for (int k = 0; k < 16; k++) {
            float a[8], bv[8];
#pragma unroll
            for (int i = 0; i < 8; i++) a[i]  = As[k][ty + 16 * i];
#pragma unroll
            for (int j = 0; j < 8; j++) bv[j] = Bs[k][tx + 16 * j];
#pragma unroll
            for (int i = 0; i < 8; i++)
#pragma unroll
                for (int j = 0; j < 8; j++) acc[i][j] = fmaf(a[i], bv[j], acc[i][j]);
        }
        __syncthreads();
    }

#pragma unroll
    for (int i = 0; i < 8; i++) {
        long r = row0 + ty + 16 * i;
#pragma unroll
        for (int j = 0; j < 8; j++) {
            int c = col0 + tx + 16 * j;
            g_pred[r * 512 + c] = acc[i][j] + bias[c];
        }
    }
}

// ---------------- kernel B: per-l 128x128x512 GEMM + acc + logits ----------------
// l_neg[n,m] = sum_c t[n, l+STEP, c] * pred[m*LS + l, c]
template<int LS, int STEP, int LOFF, int CIDX>
__global__ __launch_bounds__(256) void k_lneg(const float* __restrict__ tsteps,
                                              float* __restrict__ out) {
    extern __shared__ float sm[];
    float* As_ = sm;            // [16][128]
    float* Bs_ = sm + 2048;     // [16][128]

    const int tid = threadIdx.x;
    const int tx = tid & 15, ty = tid >> 4;
    const int l = blockIdx.x;

    const float* Abase = tsteps + (long)(l + STEP) * 512;   // + n * (1024*512)
    const float* Bbase = g_pred + (long)l * 512;            // + m * (LS*512)

    float acc[8][8];
#pragma unroll
    for (int i = 0; i < 8; i++)
#pragma unroll
        for (int j = 0; j < 8; j++) acc[i][j] = 0.0f;

    for (int k0 = 0; k0 < 512; k0 += 16) {
#pragma unroll
        for (int i = 0; i < 2; i++) {
            int f4 = tid + i * 256;
            int m  = f4 >> 2;
            int k4 = (f4 & 3) * 4;
            float4 va = *(const float4*)(Abase + (long)m * (1024 * 512) + k0 + k4);
            As_[(k4 + 0) * 128 + m] = va.x; As_[(k4 + 1) * 128 + m] = va.y;
            As_[(k4 + 2) * 128 + m] = va.z; As_[(k4 + 3) * 128 + m] = va.w;
            float4 vb = *(const float4*)(Bbase + (long)m * (LS * 512) + k0 + k4);
            Bs_[(k4 + 0) * 128 + m] = vb.x; Bs_[(k4 + 1) * 128 + m] = vb.y;
            Bs_[(k4 + 2) * 128 + m] = vb.z; Bs_[(k4 + 3) * 128 + m] = vb.w;
        }
        __syncthreads();
#pragma unroll
        for (int k = 0; k < 16; k++) {
            float a[8], bv[8];
#pragma unroll
            for (int i = 0; i < 8; i++) a[i]  = As_[k * 128 + ty + 16 * i];
#pragma unroll
            for (int j = 0; j < 8; j++) bv[j] = Bs_[k * 128 + tx + 16 * j];
#pragma unroll
            for (int i = 0; i < 8; i++)
#pragma unroll
                for (int j = 0; j < 8; j++) acc[i][j] = fmaf(a[i], bv[j], acc[i][j]);
        }
        __syncthreads();
    }

    // stage full 128x128 tile in smem (overlays GEMM tiles; safe after last sync)
    float* sC = sm;  // [128][129]
#pragma unroll
    for (int i = 0; i < 8; i++) {
        int n = ty + 16 * i;
#pragma unroll
        for (int j = 0; j < 8; j++) {
            int m = tx + 16 * j;
            sC[n * 129 + m] = acc[i][j];
        }
    }
    __syncthreads();

    // NCE accuracy: row n wins iff sC[n][n] > sC[n][m] for all m != n
    if (tid < 128) {
        int n = tid;
        float pos = sC[n * 129 + n];
        bool win = true;
#pragma unroll 8
        for (int m = 0; m < 128; m++) {
            if (m != n && !(pos > sC[n * 129 + m])) win = false;
        }
        unsigned bal = __ballot_sync(0xffffffffu, win);
        if ((tid & 31) == 0) atomicAdd(&g_cnt[CIDX], (unsigned)__popc(bal));
    }

    // write logits = l_neg / 0.07 at out[(n*128 + m)*2045 + LOFF + l]
    const float invT = 1.0f / 0.07f;
    for (int idx = tid; idx < 128 * 128; idx += 256) {
        int n = idx >> 7, m = idx & 127;
        out[((long)(n * 128 + m)) * 2045 + LOFF + l] = sC[n * 129 + m] * invT;
    }
}

// ---------------- launch ----------------
extern "C" void kernel_launch(void* const* d_in, const int* in_sizes, int n_in,
                              void* d_out, int out_size) {
    const float* ts = (const float*)d_in[0];   // timesteps         (128,1024,512)
    const float* pt = (const float*)d_in[1];   // patient_timesteps (128,1024,512)
    const float* W1 = (const float*)d_in[2];   // (512,512)
    const float* b1 = (const float*)d_in[3];   // (512,)
    const float* W2 = (const float*)d_in[4];
    const float* b2 = (const float*)d_in[5];
    float* out = (float*)d_out;

    const int smemC = 128 * 129 * sizeof(float);   // 66048 bytes
    cudaFuncSetAttribute(k_lneg<L1, 1, 0, 0>,    cudaFuncAttributeMaxDynamicSharedMemorySize, smemC);
    cudaFuncSetAttribute(k_lneg<L2, 2, L1, 1>,   cudaFuncAttributeMaxDynamicSharedMemorySize, smemC);

    k_zero<<<1, 32>>>();
    k_ytrues<<<(int)((YTRUE_SIZE + 255) / 256), 256>>>(out);

    // step 1
    k_pred<L1><<<dim3(4, L1), 256>>>(pt, W1, b1);
    k_lneg<L1, 1, 0, 0><<<L1, 256, smemC>>>(ts, out);

    // step 2
    k_pred<L2><<<dim3(4, L2), 256>>>(pt, W2, b2);
    k_lneg<L2, 2, L1, 1><<<L2, 256, smemC>>>(ts, out);

    k_accs<<<1, 32>>>(out);
}

// round 3
// speedup vs baseline: 6.1014x; 6.1014x over previous
#include <cuda_runtime.h>
#include <cuda_fp16.h>
#include <cstdint>

// ---------------- problem constants ----------------
#define L1c 1023
#define L2c 1022
#define YTRUE_OFF  33505280l
#define YTRUE_SIZE 261760l
#define ACC_OFF    33767040l

// ---------------- scratch (__device__ globals; no allocs allowed) ----------------
static __device__ __half g_ts16[128ll * 1024 * 512];   // timesteps f16, 134MB
static __device__ __half g_pt16[128ll * 1024 * 512];   // patient f16, 134MB
static __device__ __half g_pred16[128ll * 1024 * 512]; // pred f16 [m][l][c], 134MB
static __device__ __half g_w16[2ll * 512 * 512];       // W1,W2 f16
static __device__ float  g_lneg[1023ll * 128 * 128];   // [l][n*128+m], 67MB
static __device__ unsigned int g_cnt[2];

// ---------------- PTX helpers (family-portable only: no tcgen05) ----------------
__device__ __forceinline__ uint32_t s2u(const void* p) {
    uint32_t a;
    asm("{ .reg .u64 t; cvta.to.shared.u64 t, %1; cvt.u32.u64 %0, t; }" : "=r"(a) : "l"(p));
    return a;
}
__device__ __forceinline__ void cp16(uint32_t dst, const void* src) {
    asm volatile("cp.async.cg.shared.global [%0], [%1], 16;" :: "r"(dst), "l"(src));
}
#define CP_COMMIT() asm volatile("cp.async.commit_group;" ::: "memory")

__device__ __forceinline__ void ldsm4(uint32_t addr, uint32_t& r0, uint32_t& r1,
                                      uint32_t& r2, uint32_t& r3) {
    asm volatile("ldmatrix.sync.aligned.m8n8.x4.shared.b16 {%0,%1,%2,%3}, [%4];"
                 : "=r"(r0), "=r"(r1), "=r"(r2), "=r"(r3) : "r"(addr));
}
__device__ __forceinline__ void mma16816(float* d, const uint32_t* a, uint32_t b0, uint32_t b1) {
    asm volatile(
        "mma.sync.aligned.m16n8k16.row.col.f32.f16.f16.f32 "
        "{%0,%1,%2,%3}, {%4,%5,%6,%7}, {%8,%9}, {%0,%1,%2,%3};"
        : "+f"(d[0]), "+f"(d[1]), "+f"(d[2]), "+f"(d[3])
        : "r"(a[0]), "r"(a[1]), "r"(a[2]), "r"(a[3]), "r"(b0), "r"(b1));
}

// ---------------- stage geometry ----------------
// stage: A[128 rows][64 halves, padded to 144B/row] + B same.
#define ROWB   144u
#define MATB   (128u * ROWB)          // 18432
#define STB    (2u * MATB)            // 36864 per stage
#define NSTG   3
#define DSMEM  (NSTG * STB)           // 110592

// issue one ktile stage: each thread copies 4 A segs + 4 B segs (16B each)
__device__ __forceinline__ void issue_stage(uint32_t sbase, int tid,
                                            const __half* const* aP,
                                            const __half* const* bP, int koff) {
    const uint32_t seg = (uint32_t)(tid & 7) * 16u;
#pragma unroll
    for (int i = 0; i < 4; i++) {
        uint32_t r = (uint32_t)(tid >> 3) + 32u * i;
        cp16(sbase + r * ROWB + seg, aP[i] + koff);
        cp16(sbase + MATB + r * ROWB + seg, bP[i] + koff);
    }
}

// compute one 64-half ktile stage into acc
__device__ __forceinline__ void compute_stage(uint32_t sbase, int wm, int wn, int lane,
                                              float acc[2][8][4]) {
    const uint32_t Ab = sbase, Bb = sbase + MATB;
    const uint32_t roff = (uint32_t)(((lane >> 3) & 1) * 8 + (lane & 7)) * ROWB;
    const uint32_t koffl = (uint32_t)(((lane >> 4) & 1) * 16);
#pragma unroll
    for (int kk = 0; kk < 4; kk++) {
        const uint32_t kb = (uint32_t)kk * 32u + koffl;
        uint32_t a[2][4];
#pragma unroll
        for (int mt = 0; mt < 2; mt++)
            ldsm4(Ab + (uint32_t)(wm * 32 + mt * 16) * ROWB + roff + kb,
                  a[mt][0], a[mt][1], a[mt][2], a[mt][3]);
        uint32_t b[4][4];
#pragma unroll
        for (int p = 0; p < 4; p++)
            ldsm4(Bb + (uint32_t)(wn * 64 + p * 16) * ROWB + roff + kb,
                  b[p][0], b[p][1], b[p][2], b[p][3]);
#pragma unroll
        for (int mt = 0; mt < 2; mt++)
#pragma unroll
            for (int nt = 0; nt < 8; nt++)
                mma16816(acc[mt][nt], a[mt], b[nt >> 1][nt & 1], b[nt >> 1][2 + (nt & 1)]);
    }
}

// mainloop macro body (identical structure in both GEMM kernels)
#define GEMM_MAINLOOP(base, aP, bP)                                          \
    issue_stage(base, tid, aP, bP, 0);   CP_COMMIT();                        \
    issue_stage(base + STB, tid, aP, bP, 64); CP_COMMIT();                   \
    _Pragma("unroll")                                                        \
    for (int kc = 0; kc < 8; kc++) {                                         \
        if (kc < 7) asm volatile("cp.async.wait_group 1;" ::: "memory");     \
        else        asm volatile("cp.async.wait_group 0;" ::: "memory");     \
        __syncthreads();                                                     \
        compute_stage(base + (uint32_t)(kc % 3) * STB, wm, wn, lane, acc);   \
        __syncthreads();                                                     \
        if (kc + 2 < 8) {                                                    \
            issue_stage(base + (uint32_t)((kc + 2) % 3) * STB, tid, aP, bP,  \
                        (kc + 2) * 64);                                      \
            CP_COMMIT();                                                     \
        }                                                                    \
    }

// ---------------- tiny helper kernels ----------------
__global__ void k_zero() { if (threadIdx.x < 2) g_cnt[threadIdx.x] = 0u; }

__global__ void k_ytrues(float* __restrict__ out) {
    long idx = (long)blockIdx.x * blockDim.x + threadIdx.x;
    if (idx < YTRUE_SIZE) out[YTRUE_OFF + idx] = (float)(idx / 2045);
}

__global__ void k_accs(float* __restrict__ out) {
    if (threadIdx.x == 0) out[ACC_OFF + 0] = (float)g_cnt[0] * (1.0f / (128.0f * 1023.0f));
    if (threadIdx.x == 1) out[ACC_OFF + 1] = (float)g_cnt[1] * (1.0f / (128.0f * 1022.0f));
}

// f32 -> f16 conversion into device-global scratch (dst_sel: 0=ts16,1=pt16,2=W1,3=W2)
__global__ void k_cvt(const float* __restrict__ src, long n4, int dst_sel) {
    __half* dst = (dst_sel == 0) ? g_ts16 : (dst_sel == 1) ? g_pt16
                 : g_w16 + (long)(dst_sel - 2) * 262144;
    long i = (long)blockIdx.x * blockDim.x + threadIdx.x;
    long stride = (long)gridDim.x * blockDim.x;
    for (; i < n4; i += stride) {
        float4 v = ((const float4*)src)[i];
        __half2 h0 = __floats2half2_rn(v.x, v.y);
        __half2 h1 = __floats2half2_rn(v.z, v.w);
        uint2 u;
        u.x = *reinterpret_cast<unsigned*>(&h0);
        u.y = *reinterpret_cast<unsigned*>(&h1);
        ((uint2*)dst)[i] = u;
    }
}

// ---------------- k_pred: pred16[m][l][c] = P[m,l,:] . W[c,:] + b[c] ----------------
// grid (4 c-blocks, 8 l-blocks, 128 m). A rows contiguous in l.
template<int STEP>
__global__ __launch_bounds__(256, 2) void k_pred(const float* __restrict__ bias) {
    extern __shared__ char dsm[];
    __shared__ float sb[128];
    const int tid = threadIdx.x;
    const int lane = tid & 31, wid = tid >> 5, wm = wid & 3, wn = wid >> 2;
    const int c0 = blockIdx.x * 128;
    const int l0 = blockIdx.y * 128;
    const int m  = blockIdx.z;
    const uint32_t base = s2u(dsm);
    const __half* w16 = g_w16 + (long)STEP * 262144;

    if (tid < 128) sb[tid] = bias[c0 + tid];

    const __half* aP[4]; const __half* bP[4];
#pragma unroll
    for (int i = 0; i < 4; i++) {
        int r = (tid >> 3) + 32 * i;
        aP[i] = g_pt16 + ((long)(m * 1024 + l0 + r)) * 512 + (tid & 7) * 8;
        bP[i] = w16 + ((long)(c0 + r)) * 512 + (tid & 7) * 8;
    }

    float acc[2][8][4] = {};
    GEMM_MAINLOOP(base, aP, bP)

    // epilogue: +bias, f16 store to g_pred16
#pragma unroll
    for (int mt = 0; mt < 2; mt++) {
        int mrow = wm * 32 + mt * 16 + (lane >> 2);
#pragma unroll
        for (int nt = 0; nt < 8; nt++) {
            int cl = wn * 64 + nt * 8 + (lane & 3) * 2;
            long gr = (long)(m * 1024 + l0 + mrow);
            __half2 h01 = __floats2half2_rn(acc[mt][nt][0] + sb[cl],
                                            acc[mt][nt][1] + sb[cl + 1]);
            *(__half2*)&g_pred16[gr * 512 + c0 + cl] = h01;
            __half2 h23 = __floats2half2_rn(acc[mt][nt][2] + sb[cl],
                                            acc[mt][nt][3] + sb[cl + 1]);
            *(__half2*)&g_pred16[(gr + 8) * 512 + c0 + cl] = h23;
        }
    }
}

// ---------------- k_lneg: per-l 128(n)x128(m)x512 + accuracy + scratch ----------------
template<int LS, int STEP, int CIDX>
__global__ __launch_bounds__(256, 2) void k_lneg() {
    extern __shared__ char dsm[];
    const int tid = threadIdx.x;
    const int lane = tid & 31, wid = tid >> 5, wm = wid & 3, wn = wid >> 2;
    const int l = blockIdx.x;
    const uint32_t base = s2u(dsm);

    const __half* aP[4]; const __half* bP[4];
#pragma unroll
    for (int i = 0; i < 4; i++) {
        int r = (tid >> 3) + 32 * i;
        aP[i] = g_ts16 + ((long)(r * 1024 + l + STEP)) * 512 + (tid & 7) * 8;   // n rows
        bP[i] = g_pred16 + ((long)(r * 1024 + l)) * 512 + (tid & 7) * 8;        // m rows
    }

    float acc[2][8][4] = {};
    GEMM_MAINLOOP(base, aP, bP)

    // stage D tile in smem (reuses pipeline buffers; all stages consumed)
    float* sC = (float*)dsm;  // [128][129]
#pragma unroll
    for (int mt = 0; mt < 2; mt++) {
        int n = wm * 32 + mt * 16 + (lane >> 2);
#pragma unroll
        for (int nt = 0; nt < 8; nt++) {
            int mc = wn * 64 + nt * 8 + (lane & 3) * 2;
            sC[n * 129 + mc]           = acc[mt][nt][0];
            sC[n * 129 + mc + 1]       = acc[mt][nt][1];
            sC[(n + 8) * 129 + mc]     = acc[mt][nt][2];
            sC[(n + 8) * 129 + mc + 1] = acc[mt][nt][3];
        }
    }
    __syncthreads();

    // NCE accuracy
    if (tid < 128) {
        float pos = sC[tid * 129 + tid];
        bool win = true;
#pragma unroll 8
        for (int mm = 0; mm < 128; mm++)
            if (mm != tid && !(pos > sC[tid * 129 + mm])) win = false;
        unsigned bal = __ballot_sync(0xffffffffu, win);
        if ((tid & 31) == 0) atomicAdd(&g_cnt[CIDX], (unsigned)__popc(bal));
    }

    // scaled logits to scratch (coalesced)
    const float invT = 1.0f / 0.07f;
    for (int idx = tid; idx < 128 * 128; idx += 256) {
        int n = idx >> 7, mm = idx & 127;
        g_lneg[(long)l * 16384 + idx] = sC[n * 129 + mm] * invT;
    }
}

// ---------------- k_tr: scratch [l][nm] -> out [nm][LOFF+l] ----------------
template<int LS, long LOFF>
__global__ __launch_bounds__(256) void k_tr(float* __restrict__ out) {
    __shared__ float t[32][257];
    const int tid = threadIdx.x;
    const int nm0 = blockIdx.x * 256;
    const int l0 = blockIdx.y * 32;
#pragma unroll 4
    for (int i = 0; i < 32; i++) {
        int l = l0 + i;
        if (l < LS) t[i][tid] = g_lneg[(long)l * 16384 + nm0 + tid];
    }
    __syncthreads();
    const int w = tid >> 5, lane = tid & 31;
    const int l = l0 + lane;
    if (l < LS) {
#pragma unroll 4
        for (int q = 0; q < 32; q++) {
            int nm = w * 32 + q;
            out[(long)(nm0 + nm) * 2045 + LOFF + l] = t[lane][nm];
        }
    }
}

// ---------------- launch ----------------
extern "C" void kernel_launch(void* const* d_in, const int* in_sizes, int n_in,
                              void* d_out, int out_size) {
    const float* ts = (const float*)d_in[0];
    const float* pt = (const float*)d_in[1];
    const float* W1 = (const float*)d_in[2];
    const float* b1 = (const float*)d_in[3];
    const float* W2 = (const float*)d_in[4];
    const float* b2 = (const float*)d_in[5];
    float* out = (float*)d_out;

    cudaFuncSetAttribute(k_pred<0>, cudaFuncAttributeMaxDynamicSharedMemorySize, DSMEM);
    cudaFuncSetAttribute(k_pred<1>, cudaFuncAttributeMaxDynamicSharedMemorySize, DSMEM);
    cudaFuncSetAttribute(k_lneg<L1c, 1, 0>, cudaFuncAttributeMaxDynamicSharedMemorySize, DSMEM);
    cudaFuncSetAttribute(k_lneg<L2c, 2, 1>, cudaFuncAttributeMaxDynamicSharedMemorySize, DSMEM);

    k_zero<<<1, 32>>>();
    k_ytrues<<<(int)((YTRUE_SIZE + 255) / 256), 256>>>(out);

    const long n4big = 128l * 1024 * 512 / 4;   // 16,777,216 float4s
    k_cvt<<<16384, 256>>>(ts, n4big, 0);
    k_cvt<<<16384, 256>>>(pt, n4big, 1);
    k_cvt<<<256, 256>>>(W1, 65536, 2);
    k_cvt<<<256, 256>>>(W2, 65536, 3);

    // step 1
    k_pred<0><<<dim3(4, 8, 128), 256, DSMEM>>>(b1);
    k_lneg<L1c, 1, 0><<<L1c, 256, DSMEM>>>();
    k_tr<L1c, 0l><<<dim3(64, 32), 256>>>(out);

    // step 2
    k_pred<1><<<dim3(4, 8, 128), 256, DSMEM>>>(b2);
    k_lneg<L2c, 2, 1><<<L2c, 256, DSMEM>>>();
    k_tr<L2c, 1023l><<<dim3(64, 32), 256>>>(out);

    k_accs<<<1, 32>>>(out);
}